// round 3
// baseline (speedup 1.0000x reference)
#include <cuda_runtime.h>

// Problem constants
#define B_   2
#define T_   2048
#define D_   1024
#define H_   16
#define HD_  64
#define M_   (B_ * T_)       // 4096
#define NQKV (3 * D_)        // 3072

// Scratch buffers (allocation-free rule: __device__ globals)
__device__ float g_Q[B_ * H_ * T_ * HD_];   // (b,h,t,d)
__device__ float g_K[B_ * H_ * T_ * HD_];
__device__ float g_V[B_ * H_ * T_ * HD_];
__device__ float g_O[B_ * T_ * D_];         // (b,t,h*HD+d)

// ---------------------------------------------------------------------------
// Tiled SGEMM: C = A @ W^T + bias.  A is MxK row-major, W is NxK row-major.
// MODE 0: A = x, scatter output into g_Q/g_K/g_V in (b,h,t,d) layout.
// MODE 1: A = g_O (ignores the A arg), plain store to out.
// BM=BN=128, BK=16, 256 threads, 8x8 register tile per thread.
// ---------------------------------------------------------------------------
template <int MODE>
__global__ __launch_bounds__(256)
void gemm_kernel(const float* __restrict__ A, const float* __restrict__ W,
                 const float* __restrict__ bias, float* __restrict__ out,
                 int M, int N, int K)
{
    __shared__ float As[16][132];   // K-transposed A tile (pad vs bank conflicts)
    __shared__ float Ws[16][132];   // K-transposed W tile

    const int tid = threadIdx.x;
    const int tx  = tid & 15;
    const int ty  = tid >> 4;
    const int tm0 = ty << 3;
    const int tn0 = tx << 3;
    const int m0  = blockIdx.y << 7;
    const int n0  = blockIdx.x << 7;

    const float* Ap = (MODE == 1 ? (const float*)g_O : A) + m0 * K;
    const float* Wp = W + n0 * K;

    float acc[8][8];
#pragma unroll
    for (int i = 0; i < 8; i++)
#pragma unroll
        for (int j = 0; j < 8; j++) acc[i][j] = 0.f;

    for (int k0 = 0; k0 < K; k0 += 16) {
        // Cooperative load: 128x16 of A and W, coalesced float4 along K,
        // stored transposed As[kk][m] / Ws[kk][n].
#pragma unroll
        for (int i = 0; i < 2; i++) {
            int f   = tid + (i << 8);
            int row = f >> 2;
            int kc  = (f & 3) << 2;
            float4 av = *(const float4*)(Ap + row * K + k0 + kc);
            As[kc + 0][row] = av.x;
            As[kc + 1][row] = av.y;
            As[kc + 2][row] = av.z;
            As[kc + 3][row] = av.w;
            float4 wv = *(const float4*)(Wp + row * K + k0 + kc);
            Ws[kc + 0][row] = wv.x;
            Ws[kc + 1][row] = wv.y;
            Ws[kc + 2][row] = wv.z;
            Ws[kc + 3][row] = wv.w;
        }
        __syncthreads();

#pragma unroll
        for (int kk = 0; kk < 16; kk++) {
            float a[8], b[8];
            *(float4*)(a)     = *(const float4*)(&As[kk][tm0]);
            *(float4*)(a + 4) = *(const float4*)(&As[kk][tm0 + 4]);
            *(float4*)(b)     = *(const float4*)(&Ws[kk][tn0]);
            *(float4*)(b + 4) = *(const float4*)(&Ws[kk][tn0 + 4]);
#pragma unroll
            for (int i = 0; i < 8; i++)
#pragma unroll
                for (int j = 0; j < 8; j++)
                    acc[i][j] = fmaf(a[i], b[j], acc[i][j]);
        }
        __syncthreads();
    }

    // Epilogue
#pragma unroll
    for (int i = 0; i < 8; i++) {
        int m  = m0 + tm0 + i;
        int bb = m >> 11;          // m / T_
        int t  = m & (T_ - 1);
#pragma unroll
        for (int j = 0; j < 8; j++) {
            int n   = n0 + tn0 + j;
            float v = acc[i][j] + bias[n];
            if (MODE == 0) {
                int part = n >> 10;          // 0=Q 1=K 2=V
                int c    = n & (D_ - 1);
                int h    = c >> 6;
                int d    = c & (HD_ - 1);
                float* dst = (part == 0) ? g_Q : ((part == 1) ? g_K : g_V);
                dst[((bb * H_ + h) * T_ + t) * HD_ + d] = v;
            } else {
                out[m * N + n] = v;
            }
        }
    }
}

// ---------------------------------------------------------------------------
// Flash-attention (causal), fp32. One CTA = 64 queries of one (b,h).
// 256 threads as 16x16; each thread owns a 4x4 tile of the 64x64 S block
// and a 4x4 tile of the 64x64 O accumulator. K, Q, P stored transposed in
// smem (stride 68) so all compute-phase reads are conflict-free LDS.128.
// ---------------------------------------------------------------------------
#define SQ 68
#define ATTN_SMEM ((3 * 64 * SQ + 64 * 64) * (int)sizeof(float))

__global__ __launch_bounds__(256)
void attn_kernel()
{
    extern __shared__ float sm[];
    float* Qt = sm;                 // [64(d)][SQ] : Qt[d][r] = Q[r][d]
    float* Kt = Qt + 64 * SQ;       // [64(d)][SQ] : Kt[d][c] = K[c][d]
    float* Pt = Kt + 64 * SQ;       // [64(c)][SQ] : Pt[c][r] = P[r][c]
    float* Vs = Pt + 64 * SQ;       // [64(c)][64] : Vs[c][d]

    const int tid = threadIdx.x;
    const int tx  = tid & 15;
    const int ty  = tid >> 4;
    const int r0  = ty << 2;        // query rows owned (4)
    const int c0  = tx << 2;        // key cols / out dims owned (4)
    const int qb  = (int)gridDim.x - 1 - (int)blockIdx.x;  // heavy blocks first
    const int bh  = blockIdx.y;     // b*H + h
    const int q0  = qb << 6;
    const int base = bh * (T_ * HD_);
    const float scale = 0.125f;     // 1/sqrt(64)

    // Load Q tile, transposed into smem (coalesced global read, one-time scatter)
#pragma unroll
    for (int i = 0; i < 4; i++) {
        int f = tid + (i << 8);
        int r = f >> 4;
        int d = (f & 15) << 2;
        float4 v = *(const float4*)(g_Q + base + (q0 + r) * HD_ + d);
        Qt[(d + 0) * SQ + r] = v.x;
        Qt[(d + 1) * SQ + r] = v.y;
        Qt[(d + 2) * SQ + r] = v.z;
        Qt[(d + 3) * SQ + r] = v.w;
    }

    float m_i[4], l_i[4], acc[4][4];
#pragma unroll
    for (int i = 0; i < 4; i++) {
        m_i[i] = -1e30f;
        l_i[i] = 0.f;
#pragma unroll
        for (int j = 0; j < 4; j++) acc[i][j] = 0.f;
    }

    for (int jb = 0; jb <= qb; jb++) {
        __syncthreads();            // previous iter's Pt/Vs reads done
        const int kb0 = jb << 6;

        // Load K (transposed) and V tiles
#pragma unroll
        for (int i = 0; i < 4; i++) {
            int f = tid + (i << 8);
            int r = f >> 4;
            int d = (f & 15) << 2;
            float4 kv = *(const float4*)(g_K + base + (kb0 + r) * HD_ + d);
            Kt[(d + 0) * SQ + r] = kv.x;
            Kt[(d + 1) * SQ + r] = kv.y;
            Kt[(d + 2) * SQ + r] = kv.z;
            Kt[(d + 3) * SQ + r] = kv.w;
            float4 vv = *(const float4*)(g_V + base + (kb0 + r) * HD_ + d);
            *(float4*)(&Vs[r * 64 + d]) = vv;
        }
        __syncthreads();

        // S = Q K^T (64x64x64), 4x4 per thread
        float s[4][4];
#pragma unroll
        for (int i = 0; i < 4; i++)
#pragma unroll
            for (int j = 0; j < 4; j++) s[i][j] = 0.f;

#pragma unroll 8
        for (int kk = 0; kk < 64; kk++) {
            float q[4], k[4];
            *(float4*)q = *(const float4*)(&Qt[kk * SQ + r0]);   // broadcast
            *(float4*)k = *(const float4*)(&Kt[kk * SQ + c0]);   // conflict-free
#pragma unroll
            for (int i = 0; i < 4; i++)
#pragma unroll
                for (int j = 0; j < 4; j++)
                    s[i][j] = fmaf(q[i], k[j], s[i][j]);
        }

        // scale + causal mask (only diagonal block needs masking)
        const bool diag = (jb == qb);
#pragma unroll
        for (int i = 0; i < 4; i++) {
            int qi = q0 + r0 + i;
#pragma unroll
            for (int j = 0; j < 4; j++) {
                int ki = kb0 + c0 + j;
                s[i][j] = (diag && ki > qi) ? -1e30f : s[i][j] * scale;
            }
        }

        // Online softmax update (row stats replicated across the 16 tx lanes)
#pragma unroll
        for (int i = 0; i < 4; i++) {
            float mx = fmaxf(fmaxf(s[i][0], s[i][1]), fmaxf(s[i][2], s[i][3]));
#pragma unroll
            for (int off = 8; off >= 1; off >>= 1)
                mx = fmaxf(mx, __shfl_xor_sync(0xffffffffu, mx, off, 16));
            float mnew = fmaxf(m_i[i], mx);
            float sum = 0.f;
#pragma unroll
            for (int j = 0; j < 4; j++) {
                s[i][j] = __expf(s[i][j] - mnew);
                sum += s[i][j];
            }
#pragma unroll
            for (int off = 8; off >= 1; off >>= 1)
                sum += __shfl_xor_sync(0xffffffffu, sum, off, 16);
            float fac = __expf(m_i[i] - mnew);
            l_i[i] = l_i[i] * fac + sum;
            m_i[i] = mnew;
#pragma unroll
            for (int j = 0; j < 4; j++) acc[i][j] *= fac;
        }

        // Write P transposed
#pragma unroll
        for (int i = 0; i < 4; i++)
#pragma unroll
            for (int j = 0; j < 4; j++)
                Pt[(c0 + j) * SQ + (r0 + i)] = s[i][j];
        __syncthreads();

        // O += P V (64x64x64)
#pragma unroll 8
        for (int c = 0; c < 64; c++) {
            float p[4], v[4];
            *(float4*)p = *(const float4*)(&Pt[c * SQ + r0]);    // broadcast
            *(float4*)v = *(const float4*)(&Vs[c * 64 + c0]);    // conflict-free
#pragma unroll
            for (int i = 0; i < 4; i++)
#pragma unroll
                for (int j = 0; j < 4; j++)
                    acc[i][j] = fmaf(p[i], v[j], acc[i][j]);
        }
    }

    // Final normalize + store to g_O in (b, t, h*HD+d) layout
    const int bb = bh >> 4;
    const int h  = bh & 15;
#pragma unroll
    for (int i = 0; i < 4; i++) {
        float inv = 1.0f / l_i[i];
        int t = q0 + r0 + i;
        float4 o;
        o.x = acc[i][0] * inv;
        o.y = acc[i][1] * inv;
        o.z = acc[i][2] * inv;
        o.w = acc[i][3] * inv;
        *(float4*)(g_O + (bb * T_ + t) * D_ + h * HD_ + c0) = o;
    }
}

// ---------------------------------------------------------------------------
// kernel_launch: QKV GEMM -> attention -> output projection
// ---------------------------------------------------------------------------
extern "C" void kernel_launch(void* const* d_in, const int* in_sizes, int n_in,
                              void* d_out, int out_size)
{
    (void)in_sizes; (void)n_in; (void)out_size;
    const float* x     = (const float*)d_in[0];
    const float* Wqkv  = (const float*)d_in[1];
    const float* bqkv  = (const float*)d_in[2];
    const float* Wproj = (const float*)d_in[3];
    const float* bproj = (const float*)d_in[4];
    float* out = (float*)d_out;

    // idempotent, host-side only — safe under graph capture
    cudaFuncSetAttribute(attn_kernel,
                         cudaFuncAttributeMaxDynamicSharedMemorySize, ATTN_SMEM);

    gemm_kernel<0><<<dim3(NQKV / 128, M_ / 128), 256>>>(x, Wqkv, bqkv, nullptr,
                                                        M_, NQKV, D_);
    attn_kernel<<<dim3(T_ / 64, B_ * H_), 256, ATTN_SMEM>>>();
    gemm_kernel<1><<<dim3(D_ / 128, M_ / 128), 256>>>(nullptr, Wproj, bproj, out,
                                                      M_, D_, D_);
}

// round 6
// speedup vs baseline: 1.5756x; 1.5756x over previous
#include <cuda_runtime.h>
#include <cuda_bf16.h>
#include <cstdint>

// Problem constants
#define B_   2
#define T_   2048
#define D_   1024
#define H_   16
#define HD_  64
#define M_   (B_ * T_)       // 4096
#define NQKV (3 * D_)        // 3072
#define K_   D_              // 1024 (GEMM K for both GEMMs)

// ---------------------------------------------------------------------------
// Scratch (__device__ globals: allocation-free rule)
// ---------------------------------------------------------------------------
__device__ float g_Q[B_ * H_ * T_ * HD_];   // (b,h,t,d)
__device__ float g_K[B_ * H_ * T_ * HD_];
__device__ float g_V[B_ * H_ * T_ * HD_];
__device__ float g_O[B_ * T_ * D_];         // (b,t,h*HD+d)

// bf16 hi/lo split copies
__device__ __nv_bfloat16 g_xh[M_ * D_],    g_xl[M_ * D_];
__device__ __nv_bfloat16 g_wqh[NQKV * D_], g_wql[NQKV * D_];
__device__ __nv_bfloat16 g_wph[D_ * D_],   g_wpl[D_ * D_];
__device__ __nv_bfloat16 g_oh[M_ * D_],    g_ol[M_ * D_];

// ---------------------------------------------------------------------------
// Base-ISA tensor-core helpers (compile for compute_103: NO tcgen05)
// ---------------------------------------------------------------------------
__device__ __forceinline__ uint32_t smem_to_u32(const void* p) {
    uint32_t a;
    asm("{ .reg .u64 t; cvta.to.shared.u64 t, %1; cvt.u32.u64 %0, t; }"
        : "=r"(a) : "l"(p));
    return a;
}

__device__ __forceinline__ void ldsm4(uint32_t* r, uint32_t addr) {
    asm volatile("ldmatrix.sync.aligned.m8n8.x4.shared.b16 {%0,%1,%2,%3}, [%4];"
        : "=r"(r[0]), "=r"(r[1]), "=r"(r[2]), "=r"(r[3]) : "r"(addr));
}

__device__ __forceinline__ void mma16816(float* d, const uint32_t* a, const uint32_t* b) {
    asm volatile(
        "mma.sync.aligned.m16n8k16.row.col.f32.bf16.bf16.f32 "
        "{%0,%1,%2,%3}, {%4,%5,%6,%7}, {%8,%9}, {%0,%1,%2,%3};"
        : "+f"(d[0]), "+f"(d[1]), "+f"(d[2]), "+f"(d[3])
        : "r"(a[0]), "r"(a[1]), "r"(a[2]), "r"(a[3]), "r"(b[0]), "r"(b[1]));
}

#define CP_ASYNC16(s, g) \
    asm volatile("cp.async.cg.shared.global [%0], [%1], 16;" :: "r"(s), "l"(g))
#define CP_COMMIT() asm volatile("cp.async.commit_group;" ::: "memory")
#define CP_WAIT1()  asm volatile("cp.async.wait_group 1;" ::: "memory")
#define CP_WAIT0()  asm volatile("cp.async.wait_group 0;" ::: "memory")

// ---------------------------------------------------------------------------
// fp32 -> bf16 hi/lo split kernels.  SRC: 0=x, 1=W_qkv, 2=W_proj, 3=g_O
// ---------------------------------------------------------------------------
template <int SRC>
__global__ __launch_bounds__(256)
void split_kernel(const float* __restrict__ srcp, int n)
{
    const float* src = (SRC == 3) ? (const float*)g_O : srcp;
    __nv_bfloat16 *h, *l;
    if      (SRC == 0) { h = g_xh;  l = g_xl;  }
    else if (SRC == 1) { h = g_wqh; l = g_wql; }
    else if (SRC == 2) { h = g_wph; l = g_wpl; }
    else               { h = g_oh;  l = g_ol;  }

    int i = (blockIdx.x * 256 + threadIdx.x) * 4;
    if (i >= n) return;
    float4 v = *(const float4*)(src + i);
    __nv_bfloat16 h0 = __float2bfloat16(v.x);
    __nv_bfloat16 h1 = __float2bfloat16(v.y);
    __nv_bfloat16 h2 = __float2bfloat16(v.z);
    __nv_bfloat16 h3 = __float2bfloat16(v.w);
    __nv_bfloat162* hp = (__nv_bfloat162*)(h + i);
    __nv_bfloat162* lp = (__nv_bfloat162*)(l + i);
    hp[0] = __nv_bfloat162(h0, h1);
    hp[1] = __nv_bfloat162(h2, h3);
    lp[0] = __nv_bfloat162(__float2bfloat16(v.x - __bfloat162float(h0)),
                           __float2bfloat16(v.y - __bfloat162float(h1)));
    lp[1] = __nv_bfloat162(__float2bfloat16(v.z - __bfloat162float(h2)),
                           __float2bfloat16(v.w - __bfloat162float(h3)));
}

// ---------------------------------------------------------------------------
// Warp-MMA GEMM (HMMA bf16, 3-term split): C = A @ W^T + bias.
// A[M,K], W[N,K], both K-major row-major -> canonical TN recipe:
// non-trans ldmatrix for both A and B fragments, mma .row.col.
// CTA tile 128x128, BK=32, 8 warps (4m x 2n), warp tile 32x64 (2x8 frags).
// Smem rows padded to 80B (64B data + 16B) -> conflict-free ldmatrix.
// MODE 0: A=x(split), W=W_qkv(split), scatter to g_Q/g_K/g_V.
// MODE 1: A=g_O(split), W=W_proj(split), store to out.
// ---------------------------------------------------------------------------
#define ROWB        80u                  // padded row stride (bytes)
#define TILE_BYTES  (128u * ROWB)        // 10240 per sub-tile
#define STAGE_BYTES (4u * TILE_BYTES)    // Ah/Al/Bh/Bl = 40960
#define GEMM_SMEM   (2 * (int)STAGE_BYTES)
#define NCH         (K_ / 32)            // 32 K-chunks

__device__ __forceinline__ void load_stage(
    uint32_t sbase,
    const __nv_bfloat16* __restrict__ Ah, const __nv_bfloat16* __restrict__ Al,
    const __nv_bfloat16* __restrict__ Bh, const __nv_bfloat16* __restrict__ Bl,
    int m0, int n0, int k0, int tid)
{
#pragma unroll
    for (int i = 0; i < 8; ++i) {
        const int arr = i >> 1;                         // 0:Ah 1:Al 2:Bh 3:Bl
        const int row = ((i & 1) << 6) + (tid >> 2);    // 0..127
        const int ck  = tid & 3;                        // 16B chunk within row
        const __nv_bfloat16* src = (arr == 0) ? Ah : (arr == 1) ? Al
                                  : (arr == 2) ? Bh : Bl;
        const int grow = ((arr < 2) ? m0 : n0) + row;
        const void* g = (const char*)(src + (size_t)grow * K_ + k0) + ck * 16;
        uint32_t s = sbase + (uint32_t)arr * TILE_BYTES
                           + (uint32_t)row * ROWB + (uint32_t)ck * 16u;
        CP_ASYNC16(s, g);
    }
}

template <int MODE>
__global__ __launch_bounds__(256)
void gemm_wm(const float* __restrict__ bias, float* __restrict__ out)
{
    extern __shared__ char smem[];

    const __nv_bfloat16* Ah = (MODE == 0) ? g_xh  : g_oh;
    const __nv_bfloat16* Al = (MODE == 0) ? g_xl  : g_ol;
    const __nv_bfloat16* Bh = (MODE == 0) ? g_wqh : g_wph;
    const __nv_bfloat16* Bl = (MODE == 0) ? g_wql : g_wpl;

    const int tid    = threadIdx.x;
    const int wid    = tid >> 5;
    const int lane   = tid & 31;
    const int m0     = blockIdx.y << 7;
    const int n0     = blockIdx.x << 7;
    const int warp_m = (wid >> 1) * 32;
    const int warp_n = (wid & 1) * 64;
    const uint32_t sb = smem_to_u32(smem);

    // Per-lane ldmatrix row/col offsets (x4 matrix order):
    // A: matrices (mlo,klo)(mhi,klo)(mlo,khi)(mhi,khi)  -> a0..a3 fragment order
    // B: matrices (nlo,klo)(nlo,khi)(nhi,klo)(nhi,khi)  -> b frag pairs
    const int sub = lane >> 3, rin = lane & 7;
    const uint32_t a_ro = (uint32_t)((sub & 1) * 8 + rin) * ROWB
                        + (uint32_t)(sub >> 1) * 16u;
    const uint32_t b_ro = (uint32_t)((sub >> 1) * 8 + rin) * ROWB
                        + (uint32_t)(sub & 1) * 16u;

    float acc[2][8][4];
#pragma unroll
    for (int mt = 0; mt < 2; ++mt)
#pragma unroll
        for (int nt = 0; nt < 8; ++nt)
#pragma unroll
            for (int q = 0; q < 4; ++q) acc[mt][nt][q] = 0.f;

    // Prologue: stage 0 <- chunk 0
    load_stage(sb, Ah, Al, Bh, Bl, m0, n0, 0, tid);
    CP_COMMIT();

    for (int ch = 0; ch < NCH; ++ch) {
        const uint32_t st = sb + (uint32_t)(ch & 1) * STAGE_BYTES;
        __syncthreads();                       // all warps done with stage s^1
        if (ch + 1 < NCH) {
            load_stage(sb + (uint32_t)((ch + 1) & 1) * STAGE_BYTES,
                       Ah, Al, Bh, Bl, m0, n0, (ch + 1) * 32, tid);
            CP_COMMIT();
            CP_WAIT1();                        // chunk ch's group complete
        } else {
            CP_WAIT0();
        }
        __syncthreads();

#pragma unroll
        for (int ks = 0; ks < 2; ++ks) {
            uint32_t ah[2][4], alr[2][4];
#pragma unroll
            for (int mt = 0; mt < 2; ++mt) {
                uint32_t ab = st + (uint32_t)(warp_m + mt * 16) * ROWB
                                 + a_ro + (uint32_t)ks * 32u;
                ldsm4(ah[mt],  ab);
                ldsm4(alr[mt], ab + TILE_BYTES);
            }
#pragma unroll
            for (int ng = 0; ng < 4; ++ng) {
                uint32_t bh[4], blr[4];
                uint32_t bbadr = st + 2u * TILE_BYTES
                               + (uint32_t)(warp_n + ng * 16) * ROWB
                               + b_ro + (uint32_t)ks * 32u;
                ldsm4(bh,  bbadr);
                ldsm4(blr, bbadr + TILE_BYTES);
#pragma unroll
                for (int mt = 0; mt < 2; ++mt)
#pragma unroll
                    for (int hf = 0; hf < 2; ++hf) {
                        float* d = acc[mt][ng * 2 + hf];
                        mma16816(d, ah[mt],  bh  + hf * 2);   // ah*bh
                        mma16816(d, ah[mt],  blr + hf * 2);   // ah*bl
                        mma16816(d, alr[mt], bh  + hf * 2);   // al*bh
                    }
            }
        }
    }

    // Epilogue: fragment layout: d0,d1=(row,col..col+1); d2,d3=(row+8,..)
    const int qrow = lane >> 2;
    const int qcol = (lane & 3) * 2;
#pragma unroll
    for (int mt = 0; mt < 2; ++mt)
#pragma unroll
        for (int rr = 0; rr < 2; ++rr) {
            const int m  = m0 + warp_m + mt * 16 + qrow + rr * 8;
            const int bb = m >> 11;            // m / T_
            const int t  = m & (T_ - 1);
#pragma unroll
            for (int nt = 0; nt < 8; ++nt) {
                const int n = n0 + warp_n + nt * 8 + qcol;
                float2 v;
                v.x = acc[mt][nt][rr * 2 + 0] + bias[n];
                v.y = acc[mt][nt][rr * 2 + 1] + bias[n + 1];
                if (MODE == 0) {
                    const int part = n >> 10;       // 0=Q 1=K 2=V
                    const int c    = n & (D_ - 1);
                    const int h    = c >> 6;
                    const int d    = c & (HD_ - 1);
                    float* dst = (part == 0) ? g_Q : ((part == 1) ? g_K : g_V);
                    *(float2*)(dst + ((size_t)(bb * H_ + h) * T_ + t) * HD_ + d) = v;
                } else {
                    *(float2*)(out + (size_t)m * D_ + n) = v;
                }
            }
        }
}

// ---------------------------------------------------------------------------
// Flash-attention (causal), fp32 — unchanged known-good (next round's target)
// ---------------------------------------------------------------------------
#define SQ 68
#define ATTN_SMEM ((3 * 64 * SQ + 64 * 64) * (int)sizeof(float))

__global__ __launch_bounds__(256)
void attn_kernel()
{
    extern __shared__ float sm[];
    float* Qt = sm;
    float* Kt = Qt + 64 * SQ;
    float* Pt = Kt + 64 * SQ;
    float* Vs = Pt + 64 * SQ;

    const int tid = threadIdx.x;
    const int tx  = tid & 15;
    const int ty  = tid >> 4;
    const int r0  = ty << 2;
    const int c0  = tx << 2;
    const int qb  = (int)gridDim.x - 1 - (int)blockIdx.x;
    const int bh  = blockIdx.y;
    const int q0  = qb << 6;
    const int base = bh * (T_ * HD_);
    const float scale = 0.125f;

#pragma unroll
    for (int i = 0; i < 4; i++) {
        int f = tid + (i << 8);
        int r = f >> 4;
        int d = (f & 15) << 2;
        float4 v = *(const float4*)(g_Q + base + (q0 + r) * HD_ + d);
        Qt[(d + 0) * SQ + r] = v.x;
        Qt[(d + 1) * SQ + r] = v.y;
        Qt[(d + 2) * SQ + r] = v.z;
        Qt[(d + 3) * SQ + r] = v.w;
    }

    float m_i[4], l_i[4], acc[4][4];
#pragma unroll
    for (int i = 0; i < 4; i++) {
        m_i[i] = -1e30f;
        l_i[i] = 0.f;
#pragma unroll
        for (int j = 0; j < 4; j++) acc[i][j] = 0.f;
    }

    for (int jb = 0; jb <= qb; jb++) {
        __syncthreads();
        const int kb0 = jb << 6;

#pragma unroll
        for (int i = 0; i < 4; i++) {
            int f = tid + (i << 8);
            int r = f >> 4;
            int d = (f & 15) << 2;
            float4 kv = *(const float4*)(g_K + base + (kb0 + r) * HD_ + d);
            Kt[(d + 0) * SQ + r] = kv.x;
            Kt[(d + 1) * SQ + r] = kv.y;
            Kt[(d + 2) * SQ + r] = kv.z;
            Kt[(d + 3) * SQ + r] = kv.w;
            float4 vv = *(const float4*)(g_V + base + (kb0 + r) * HD_ + d);
            *(float4*)(&Vs[r * 64 + d]) = vv;
        }
        __syncthreads();

        float s[4][4];
#pragma unroll
        for (int i = 0; i < 4; i++)
#pragma unroll
            for (int j = 0; j < 4; j++) s[i][j] = 0.f;

#pragma unroll 8
        for (int kk = 0; kk < 64; kk++) {
            float q[4], k[4];
            *(float4*)q = *(const float4*)(&Qt[kk * SQ + r0]);
            *(float4*)k = *(const float4*)(&Kt[kk * SQ + c0]);
#pragma unroll
            for (int i = 0; i < 4; i++)
#pragma unroll
                for (int j = 0; j < 4; j++)
                    s[i][j] = fmaf(q[i], k[j], s[i][j]);
        }

        const bool diag = (jb == qb);
#pragma unroll
        for (int i = 0; i < 4; i++) {
            int qi = q0 + r0 + i;
#pragma unroll
            for (int j = 0; j < 4; j++) {
                int ki = kb0 + c0 + j;
                s[i][j] = (diag && ki > qi) ? -1e30f : s[i][j] * scale;
            }
        }

#pragma unroll
        for (int i = 0; i < 4; i++) {
            float mx = fmaxf(fmaxf(s[i][0], s[i][1]), fmaxf(s[i][2], s[i][3]));
#pragma unroll
            for (int off = 8; off >= 1; off >>= 1)
                mx = fmaxf(mx, __shfl_xor_sync(0xffffffffu, mx, off, 16));
            float mnew = fmaxf(m_i[i], mx);
            float sum = 0.f;
#pragma unroll
            for (int j = 0; j < 4; j++) {
                s[i][j] = __expf(s[i][j] - mnew);
                sum += s[i][j];
            }
#pragma unroll
            for (int off = 8; off >= 1; off >>= 1)
                sum += __shfl_xor_sync(0xffffffffu, sum, off, 16);
            float fac = __expf(m_i[i] - mnew);
            l_i[i] = l_i[i] * fac + sum;
            m_i[i] = mnew;
#pragma unroll
            for (int j = 0; j < 4; j++) acc[i][j] *= fac;
        }

#pragma unroll
        for (int i = 0; i < 4; i++)
#pragma unroll
            for (int j = 0; j < 4; j++)
                Pt[(c0 + j) * SQ + (r0 + i)] = s[i][j];
        __syncthreads();

#pragma unroll 8
        for (int c = 0; c < 64; c++) {
            float p[4], v[4];
            *(float4*)p = *(const float4*)(&Pt[c * SQ + r0]);
            *(float4*)v = *(const float4*)(&Vs[c * 64 + c0]);
#pragma unroll
            for (int i = 0; i < 4; i++)
#pragma unroll
                for (int j = 0; j < 4; j++)
                    acc[i][j] = fmaf(p[i], v[j], acc[i][j]);
        }
    }

    const int bb = bh >> 4;
    const int h  = bh & 15;
#pragma unroll
    for (int i = 0; i < 4; i++) {
        float inv = 1.0f / l_i[i];
        int t = q0 + r0 + i;
        float4 o;
        o.x = acc[i][0] * inv;
        o.y = acc[i][1] * inv;
        o.z = acc[i][2] * inv;
        o.w = acc[i][3] * inv;
        *(float4*)(g_O + (size_t)(bb * T_ + t) * D_ + h * HD_ + c0) = o;
    }
}

// ---------------------------------------------------------------------------
// kernel_launch: splits -> QKV GEMM(wm) -> attention -> split(O) -> proj GEMM(wm)
// ---------------------------------------------------------------------------
extern "C" void kernel_launch(void* const* d_in, const int* in_sizes, int n_in,
                              void* d_out, int out_size)
{
    (void)in_sizes; (void)n_in; (void)out_size;
    const float* x     = (const float*)d_in[0];
    const float* Wqkv  = (const float*)d_in[1];
    const float* bqkv  = (const float*)d_in[2];
    const float* Wproj = (const float*)d_in[3];
    const float* bproj = (const float*)d_in[4];
    float* out = (float*)d_out;

    cudaFuncSetAttribute(attn_kernel,
                         cudaFuncAttributeMaxDynamicSharedMemorySize, ATTN_SMEM);
    cudaFuncSetAttribute(gemm_wm<0>,
                         cudaFuncAttributeMaxDynamicSharedMemorySize, GEMM_SMEM);
    cudaFuncSetAttribute(gemm_wm<1>,
                         cudaFuncAttributeMaxDynamicSharedMemorySize, GEMM_SMEM);

    split_kernel<0><<<(M_ * D_) / 1024, 256>>>(x, M_ * D_);
    split_kernel<1><<<(NQKV * D_) / 1024, 256>>>(Wqkv, NQKV * D_);
    split_kernel<2><<<(D_ * D_) / 1024, 256>>>(Wproj, D_ * D_);

    gemm_wm<0><<<dim3(NQKV / 128, M_ / 128), 256, GEMM_SMEM>>>(bqkv, nullptr);

    attn_kernel<<<dim3(T_ / 64, B_ * H_), 256, ATTN_SMEM>>>();

    split_kernel<3><<<(M_ * D_) / 1024, 256>>>(nullptr, M_ * D_);
    gemm_wm<1><<<dim3(D_ / 128, M_ / 128), 256, GEMM_SMEM>>>(bproj, out);
}

// round 7
// speedup vs baseline: 2.6081x; 1.6553x over previous
#include <cuda_runtime.h>
#include <cuda_bf16.h>
#include <cstdint>

// Problem constants
#define B_   2
#define T_   2048
#define D_   1024
#define H_   16
#define HD_  64
#define M_   (B_ * T_)       // 4096
#define NQKV (3 * D_)        // 3072
#define K_   D_              // 1024

// ---------------------------------------------------------------------------
// Scratch (__device__ globals: allocation-free rule)
// ---------------------------------------------------------------------------
// bf16 hi/lo split inputs for the GEMMs
__device__ __nv_bfloat16 g_xh[M_ * D_],    g_xl[M_ * D_];
__device__ __nv_bfloat16 g_wqh[NQKV * D_], g_wql[NQKV * D_];
__device__ __nv_bfloat16 g_wph[D_ * D_],   g_wpl[D_ * D_];
// bf16 hi/lo Q/K/V in (b,h,t,d) layout  (written by gemm0 epilogue)
__device__ __nv_bfloat16 g_Qh[M_ * D_], g_Ql[M_ * D_];
__device__ __nv_bfloat16 g_Kh[M_ * D_], g_Kl[M_ * D_];
__device__ __nv_bfloat16 g_Vh[M_ * D_], g_Vl[M_ * D_];
// bf16 hi/lo attention output in (b,t,D) layout (written by attn epilogue)
__device__ __nv_bfloat16 g_oh[M_ * D_], g_ol[M_ * D_];

// ---------------------------------------------------------------------------
// Base-ISA tensor-core helpers (compute_103-safe: NO tcgen05)
// ---------------------------------------------------------------------------
__device__ __forceinline__ uint32_t smem_to_u32(const void* p) {
    uint32_t a;
    asm("{ .reg .u64 t; cvta.to.shared.u64 t, %1; cvt.u32.u64 %0, t; }"
        : "=r"(a) : "l"(p));
    return a;
}
__device__ __forceinline__ void ldsm4(uint32_t* r, uint32_t addr) {
    asm volatile("ldmatrix.sync.aligned.m8n8.x4.shared.b16 {%0,%1,%2,%3}, [%4];"
        : "=r"(r[0]), "=r"(r[1]), "=r"(r[2]), "=r"(r[3]) : "r"(addr));
}
__device__ __forceinline__ void ldsm4t(uint32_t* r, uint32_t addr) {
    asm volatile("ldmatrix.sync.aligned.m8n8.x4.trans.shared.b16 {%0,%1,%2,%3}, [%4];"
        : "=r"(r[0]), "=r"(r[1]), "=r"(r[2]), "=r"(r[3]) : "r"(addr));
}
__device__ __forceinline__ void mma16816(float* d, const uint32_t* a, const uint32_t* b) {
    asm volatile(
        "mma.sync.aligned.m16n8k16.row.col.f32.bf16.bf16.f32 "
        "{%0,%1,%2,%3}, {%4,%5,%6,%7}, {%8,%9}, {%0,%1,%2,%3};"
        : "+f"(d[0]), "+f"(d[1]), "+f"(d[2]), "+f"(d[3])
        : "r"(a[0]), "r"(a[1]), "r"(a[2]), "r"(a[3]), "r"(b[0]), "r"(b[1]));
}
#define CP_ASYNC16(s, g) \
    asm volatile("cp.async.cg.shared.global [%0], [%1], 16;" :: "r"(s), "l"(g))
#define CP_COMMIT() asm volatile("cp.async.commit_group;" ::: "memory")
#define CP_WAIT1()  asm volatile("cp.async.wait_group 1;" ::: "memory")
#define CP_WAIT0()  asm volatile("cp.async.wait_group 0;" ::: "memory")

__device__ __forceinline__ void split2(float x, float y, uint32_t& hi, uint32_t& lo) {
    __nv_bfloat16 hx = __float2bfloat16(x), hy = __float2bfloat16(y);
    __nv_bfloat162 hv(hx, hy);
    __nv_bfloat162 lv(__float2bfloat16(x - __bfloat162float(hx)),
                      __float2bfloat16(y - __bfloat162float(hy)));
    hi = *reinterpret_cast<uint32_t*>(&hv);
    lo = *reinterpret_cast<uint32_t*>(&lv);
}

// ---------------------------------------------------------------------------
// fp32 -> bf16 hi/lo split kernels.  SRC: 0=x, 1=W_qkv, 2=W_proj
// ---------------------------------------------------------------------------
template <int SRC>
__global__ __launch_bounds__(256)
void split_kernel(const float* __restrict__ src, int n)
{
    __nv_bfloat16 *h, *l;
    if      (SRC == 0) { h = g_xh;  l = g_xl;  }
    else if (SRC == 1) { h = g_wqh; l = g_wql; }
    else               { h = g_wph; l = g_wpl; }

    int i = (blockIdx.x * 256 + threadIdx.x) * 4;
    if (i >= n) return;
    float4 v = *(const float4*)(src + i);
    uint32_t h0, l0, h1, l1;
    split2(v.x, v.y, h0, l0);
    split2(v.z, v.w, h1, l1);
    uint32_t* hp = (uint32_t*)(h + i);
    uint32_t* lp = (uint32_t*)(l + i);
    hp[0] = h0; hp[1] = h1;
    lp[0] = l0; lp[1] = l1;
}

// ---------------------------------------------------------------------------
// Warp-MMA GEMM (HMMA bf16, 3-term split): C = A @ W^T + bias.
// MODE 0: A=x, W=W_qkv; epilogue splits to bf16 hi/lo Q/K/V in (b,h,t,d).
// MODE 1: A=attn out (g_oh/g_ol), W=W_proj; plain fp32 store to out.
// ---------------------------------------------------------------------------
#define ROWB        80u
#define TILE_BYTES  (128u * ROWB)
#define STAGE_BYTES (4u * TILE_BYTES)
#define GEMM_SMEM   (2 * (int)STAGE_BYTES)
#define NCH         (K_ / 32)

__device__ __forceinline__ void load_stage(
    uint32_t sbase,
    const __nv_bfloat16* __restrict__ Ah, const __nv_bfloat16* __restrict__ Al,
    const __nv_bfloat16* __restrict__ Bh, const __nv_bfloat16* __restrict__ Bl,
    int m0, int n0, int k0, int tid)
{
#pragma unroll
    for (int i = 0; i < 8; ++i) {
        const int arr = i >> 1;
        const int row = ((i & 1) << 6) + (tid >> 2);
        const int ck  = tid & 3;
        const __nv_bfloat16* src = (arr == 0) ? Ah : (arr == 1) ? Al
                                  : (arr == 2) ? Bh : Bl;
        const int grow = ((arr < 2) ? m0 : n0) + row;
        const void* g = (const char*)(src + (size_t)grow * K_ + k0) + ck * 16;
        uint32_t s = sbase + (uint32_t)arr * TILE_BYTES
                           + (uint32_t)row * ROWB + (uint32_t)ck * 16u;
        CP_ASYNC16(s, g);
    }
}

template <int MODE>
__global__ __launch_bounds__(256)
void gemm_wm(const float* __restrict__ bias, float* __restrict__ out)
{
    extern __shared__ char smem[];

    const __nv_bfloat16* Ah = (MODE == 0) ? g_xh  : g_oh;
    const __nv_bfloat16* Al = (MODE == 0) ? g_xl  : g_ol;
    const __nv_bfloat16* Bh = (MODE == 0) ? g_wqh : g_wph;
    const __nv_bfloat16* Bl = (MODE == 0) ? g_wql : g_wpl;

    const int tid    = threadIdx.x;
    const int wid    = tid >> 5;
    const int lane   = tid & 31;
    const int m0     = blockIdx.y << 7;
    const int n0     = blockIdx.x << 7;
    const int warp_m = (wid >> 1) * 32;
    const int warp_n = (wid & 1) * 64;
    const uint32_t sb = smem_to_u32(smem);

    const int sub = lane >> 3, rin = lane & 7;
    const uint32_t a_ro = (uint32_t)((sub & 1) * 8 + rin) * ROWB
                        + (uint32_t)(sub >> 1) * 16u;
    const uint32_t b_ro = (uint32_t)((sub >> 1) * 8 + rin) * ROWB
                        + (uint32_t)(sub & 1) * 16u;

    float acc[2][8][4];
#pragma unroll
    for (int mt = 0; mt < 2; ++mt)
#pragma unroll
        for (int nt = 0; nt < 8; ++nt)
#pragma unroll
            for (int q = 0; q < 4; ++q) acc[mt][nt][q] = 0.f;

    load_stage(sb, Ah, Al, Bh, Bl, m0, n0, 0, tid);
    CP_COMMIT();

    for (int ch = 0; ch < NCH; ++ch) {
        const uint32_t st = sb + (uint32_t)(ch & 1) * STAGE_BYTES;
        __syncthreads();
        if (ch + 1 < NCH) {
            load_stage(sb + (uint32_t)((ch + 1) & 1) * STAGE_BYTES,
                       Ah, Al, Bh, Bl, m0, n0, (ch + 1) * 32, tid);
            CP_COMMIT();
            CP_WAIT1();
        } else {
            CP_WAIT0();
        }
        __syncthreads();

#pragma unroll
        for (int ks = 0; ks < 2; ++ks) {
            uint32_t ah[2][4], alr[2][4];
#pragma unroll
            for (int mt = 0; mt < 2; ++mt) {
                uint32_t ab = st + (uint32_t)(warp_m + mt * 16) * ROWB
                                 + a_ro + (uint32_t)ks * 32u;
                ldsm4(ah[mt],  ab);
                ldsm4(alr[mt], ab + TILE_BYTES);
            }
#pragma unroll
            for (int ng = 0; ng < 4; ++ng) {
                uint32_t bh[4], blr[4];
                uint32_t bbadr = st + 2u * TILE_BYTES
                               + (uint32_t)(warp_n + ng * 16) * ROWB
                               + b_ro + (uint32_t)ks * 32u;
                ldsm4(bh,  bbadr);
                ldsm4(blr, bbadr + TILE_BYTES);
#pragma unroll
                for (int mt = 0; mt < 2; ++mt)
#pragma unroll
                    for (int hf = 0; hf < 2; ++hf) {
                        float* d = acc[mt][ng * 2 + hf];
                        mma16816(d, ah[mt],  bh  + hf * 2);
                        mma16816(d, ah[mt],  blr + hf * 2);
                        mma16816(d, alr[mt], bh  + hf * 2);
                    }
            }
        }
    }

    const int qrow = lane >> 2;
    const int qcol = (lane & 3) * 2;
#pragma unroll
    for (int mt = 0; mt < 2; ++mt)
#pragma unroll
        for (int rr = 0; rr < 2; ++rr) {
            const int m  = m0 + warp_m + mt * 16 + qrow + rr * 8;
            const int bb = m >> 11;
            const int t  = m & (T_ - 1);
#pragma unroll
            for (int nt = 0; nt < 8; ++nt) {
                const int n = n0 + warp_n + nt * 8 + qcol;
                float vx = acc[mt][nt][rr * 2 + 0] + bias[n];
                float vy = acc[mt][nt][rr * 2 + 1] + bias[n + 1];
                if (MODE == 0) {
                    const int part = n >> 10;       // 0=Q 1=K 2=V
                    const int c    = n & (D_ - 1);
                    const int h    = c >> 6;
                    const int d    = c & (HD_ - 1);
                    __nv_bfloat16 *dh, *dl;
                    if      (part == 0) { dh = g_Qh; dl = g_Ql; }
                    else if (part == 1) { dh = g_Kh; dl = g_Kl; }
                    else                { dh = g_Vh; dl = g_Vl; }
                    size_t idx = ((size_t)(bb * H_ + h) * T_ + t) * HD_ + d;
                    uint32_t hi, lo;
                    split2(vx, vy, hi, lo);
                    *(uint32_t*)(dh + idx) = hi;
                    *(uint32_t*)(dl + idx) = lo;
                } else {
                    float2 v; v.x = vx; v.y = vy;
                    *(float2*)(out + (size_t)m * D_ + n) = v;
                }
            }
        }
}

// ---------------------------------------------------------------------------
// HMMA flash-attention (causal). CTA: 128 queries of one (b,h), 8 warps x 16
// rows. KV blocks of 64, cp.async double-buffered. 3-term bf16 split on both
// QK^T and PV. S-fragments repacked in-registers as PV A-fragments.
// ---------------------------------------------------------------------------
#define AROWB        144u
#define Q_TILE_BYTES (128u * AROWB)     // 18432
#define KVT_BYTES    (64u * AROWB)      // 9216
#define ATT_STAGE    (4u * KVT_BYTES)   // Kh,Kl,Vh,Vl = 36864
#define ATT_SMEM     (int)(2u * Q_TILE_BYTES + 2u * ATT_STAGE)  // 110592

__device__ __forceinline__ void attn_load_kv(uint32_t sk, size_t base, int kb0, int tid)
{
#pragma unroll
    for (int i = 0; i < 8; ++i) {
        const int arr = i >> 1;                     // 0 Kh,1 Kl,2 Vh,3 Vl
        const int row = ((i & 1) << 5) + (tid >> 3);
        const int ck  = tid & 7;
        const __nv_bfloat16* src = (arr == 0) ? g_Kh : (arr == 1) ? g_Kl
                                  : (arr == 2) ? g_Vh : g_Vl;
        const void* g = src + base + (size_t)(kb0 + row) * HD_ + ck * 8;
        uint32_t s = sk + (uint32_t)arr * KVT_BYTES
                        + (uint32_t)row * AROWB + (uint32_t)ck * 16u;
        CP_ASYNC16(s, g);
    }
}

__global__ __launch_bounds__(256)
void attn_wm()
{
    extern __shared__ char smem[];
    const uint32_t sb   = smem_to_u32(smem);
    const uint32_t sQ   = sb;
    const uint32_t sKV0 = sb + 2u * Q_TILE_BYTES;

    const int tid    = threadIdx.x;
    const int wid    = tid >> 5;
    const int lane   = tid & 31;
    const int qb     = (int)gridDim.x - 1 - (int)blockIdx.x;   // heavy first
    const int bh     = blockIdx.y;
    const int q0     = qb << 7;
    const size_t base = (size_t)bh * (T_ * HD_);
    const int warp_m = wid * 16;
    const int nblk   = 2 * (qb + 1);
    const float scale = 0.125f;

    const int sub = lane >> 3, rin = lane & 7;
    const uint32_t a_ro = (uint32_t)((sub & 1) * 8 + rin) * AROWB
                        + (uint32_t)(sub >> 1) * 16u;   // A / trans-V pattern
    const uint32_t b_ro = (uint32_t)((sub >> 1) * 8 + rin) * AROWB
                        + (uint32_t)(sub & 1) * 16u;    // K (B) pattern

    // Q tile load (Qh | Ql), 144B rows
#pragma unroll
    for (int i = 0; i < 8; ++i) {
        const int arr = i >> 2;                     // 0 Qh, 1 Ql
        const int row = ((i & 3) << 5) + (tid >> 3);
        const int ck  = tid & 7;
        const __nv_bfloat16* src = arr ? g_Ql : g_Qh;
        const void* g = src + base + (size_t)(q0 + row) * HD_ + ck * 8;
        uint32_t s = sQ + (uint32_t)arr * Q_TILE_BYTES
                        + (uint32_t)row * AROWB + (uint32_t)ck * 16u;
        CP_ASYNC16(s, g);
    }
    CP_COMMIT();
    attn_load_kv(sKV0, base, 0, tid);
    CP_COMMIT();
    CP_WAIT1();                     // Q group done
    __syncthreads();

    // Q fragments (4 ksteps of 16 over HD=64), hi and lo
    uint32_t qh[4][4], ql[4][4];
#pragma unroll
    for (int ks = 0; ks < 4; ++ks) {
        uint32_t ab = sQ + (uint32_t)warp_m * AROWB + a_ro + (uint32_t)ks * 32u;
        ldsm4(qh[ks], ab);
        ldsm4(ql[ks], ab + Q_TILE_BYTES);
    }

    float oacc[8][4];
#pragma unroll
    for (int nt = 0; nt < 8; ++nt)
#pragma unroll
        for (int q = 0; q < 4; ++q) oacc[nt][q] = 0.f;
    float m0r = -1e30f, m1r = -1e30f, l0r = 0.f, l1r = 0.f;

    const int qrow = lane >> 2;
    const int qcol = (lane & 3) * 2;
    const int rg0  = q0 + warp_m + qrow;     // global row (and +8)

    for (int jb = 0; jb < nblk; ++jb) {
        const uint32_t st = sKV0 + (uint32_t)(jb & 1) * ATT_STAGE;
        const int kb0 = jb << 6;
        __syncthreads();
        if (jb + 1 < nblk) {
            attn_load_kv(sKV0 + (uint32_t)((jb + 1) & 1) * ATT_STAGE,
                         base, (jb + 1) << 6, tid);
            CP_COMMIT();
            CP_WAIT1();
        } else {
            CP_WAIT0();
        }
        __syncthreads();

        // ---- S = Q K^T  (16 x 64 per warp) ----
        float s[8][4];
#pragma unroll
        for (int nt = 0; nt < 8; ++nt)
#pragma unroll
            for (int q = 0; q < 4; ++q) s[nt][q] = 0.f;

#pragma unroll
        for (int ks = 0; ks < 4; ++ks)
#pragma unroll
            for (int ntile = 0; ntile < 4; ++ntile) {
                uint32_t kh[4], kl[4];
                uint32_t ad = st + (uint32_t)(ntile * 16) * AROWB
                                 + b_ro + (uint32_t)ks * 32u;
                ldsm4(kh, ad);
                ldsm4(kl, ad + KVT_BYTES);
#pragma unroll
                for (int hf = 0; hf < 2; ++hf) {
                    float* d = s[ntile * 2 + hf];
                    mma16816(d, qh[ks], kh + hf * 2);
                    mma16816(d, qh[ks], kl + hf * 2);
                    mma16816(d, ql[ks], kh + hf * 2);
                }
            }

        // ---- causal mask (only near-diagonal blocks) ----
        if (kb0 + 63 > q0 + warp_m) {
#pragma unroll
            for (int nt = 0; nt < 8; ++nt) {
                int cg = kb0 + nt * 8 + qcol;
                if (cg     > rg0)     s[nt][0] = -1e30f;
                if (cg + 1 > rg0)     s[nt][1] = -1e30f;
                if (cg     > rg0 + 8) s[nt][2] = -1e30f;
                if (cg + 1 > rg0 + 8) s[nt][3] = -1e30f;
            }
        }

        // ---- online softmax ----
        float mx0 = -1e30f, mx1 = -1e30f;
#pragma unroll
        for (int nt = 0; nt < 8; ++nt) {
            mx0 = fmaxf(mx0, fmaxf(s[nt][0], s[nt][1]));
            mx1 = fmaxf(mx1, fmaxf(s[nt][2], s[nt][3]));
        }
        mx0 = fmaxf(mx0, __shfl_xor_sync(0xffffffffu, mx0, 1));
        mx0 = fmaxf(mx0, __shfl_xor_sync(0xffffffffu, mx0, 2));
        mx1 = fmaxf(mx1, __shfl_xor_sync(0xffffffffu, mx1, 1));
        mx1 = fmaxf(mx1, __shfl_xor_sync(0xffffffffu, mx1, 2));
        float mn0 = fmaxf(m0r, mx0 * scale);
        float mn1 = fmaxf(m1r, mx1 * scale);

        uint32_t ph[8][2], pl[8][2];
        float sum0 = 0.f, sum1 = 0.f;
#pragma unroll
        for (int nt = 0; nt < 8; ++nt) {
            float p0 = __expf(fmaf(s[nt][0], scale, -mn0));
            float p1 = __expf(fmaf(s[nt][1], scale, -mn0));
            float p2 = __expf(fmaf(s[nt][2], scale, -mn1));
            float p3 = __expf(fmaf(s[nt][3], scale, -mn1));
            sum0 += p0 + p1;
            sum1 += p2 + p3;
            split2(p0, p1, ph[nt][0], pl[nt][0]);
            split2(p2, p3, ph[nt][1], pl[nt][1]);
        }
        sum0 += __shfl_xor_sync(0xffffffffu, sum0, 1);
        sum0 += __shfl_xor_sync(0xffffffffu, sum0, 2);
        sum1 += __shfl_xor_sync(0xffffffffu, sum1, 1);
        sum1 += __shfl_xor_sync(0xffffffffu, sum1, 2);

        float f0 = __expf(m0r - mn0);
        float f1 = __expf(m1r - mn1);
        l0r = l0r * f0 + sum0;
        l1r = l1r * f1 + sum1;
        m0r = mn0; m1r = mn1;
#pragma unroll
        for (int nt = 0; nt < 8; ++nt) {
            oacc[nt][0] *= f0; oacc[nt][1] *= f0;
            oacc[nt][2] *= f1; oacc[nt][3] *= f1;
        }

        // ---- O += P V  (V via ldmatrix.trans) ----
#pragma unroll
        for (int ks = 0; ks < 4; ++ks) {
            uint32_t ah[4] = { ph[2 * ks][0], ph[2 * ks][1],
                               ph[2 * ks + 1][0], ph[2 * ks + 1][1] };
            uint32_t al[4] = { pl[2 * ks][0], pl[2 * ks][1],
                               pl[2 * ks + 1][0], pl[2 * ks + 1][1] };
#pragma unroll
            for (int dnt = 0; dnt < 4; ++dnt) {
                uint32_t vh[4], vl[4];
                uint32_t ad = st + 2u * KVT_BYTES
                            + (uint32_t)(ks * 16) * AROWB
                            + a_ro + (uint32_t)dnt * 32u;
                ldsm4t(vh, ad);
                ldsm4t(vl, ad + KVT_BYTES);
#pragma unroll
                for (int hf = 0; hf < 2; ++hf) {
                    float* d = oacc[dnt * 2 + hf];
                    mma16816(d, ah, vh + hf * 2);
                    mma16816(d, al, vh + hf * 2);
                    mma16816(d, ah, vl + hf * 2);
                }
            }
        }
    }

    // ---- epilogue: normalize, split to bf16 hi/lo, store (b,t,D) ----
    const int bb = bh >> 4;
    const int h  = bh & 15;
    const float inv0 = 1.0f / l0r;
    const float inv1 = 1.0f / l1r;
    const int t0 = q0 + warp_m + qrow;
#pragma unroll
    for (int nt = 0; nt < 8; ++nt) {
        const int d = nt * 8 + qcol;
        uint32_t hi, lo;
        size_t i0 = (size_t)(bb * T_ + t0) * D_ + h * HD_ + d;
        split2(oacc[nt][0] * inv0, oacc[nt][1] * inv0, hi, lo);
        *(uint32_t*)(g_oh + i0) = hi;
        *(uint32_t*)(g_ol + i0) = lo;
        size_t i1 = (size_t)(bb * T_ + t0 + 8) * D_ + h * HD_ + d;
        split2(oacc[nt][2] * inv1, oacc[nt][3] * inv1, hi, lo);
        *(uint32_t*)(g_oh + i1) = hi;
        *(uint32_t*)(g_ol + i1) = lo;
    }
}

// ---------------------------------------------------------------------------
// kernel_launch
// ---------------------------------------------------------------------------
extern "C" void kernel_launch(void* const* d_in, const int* in_sizes, int n_in,
                              void* d_out, int out_size)
{
    (void)in_sizes; (void)n_in; (void)out_size;
    const float* x     = (const float*)d_in[0];
    const float* Wqkv  = (const float*)d_in[1];
    const float* bqkv  = (const float*)d_in[2];
    const float* Wproj = (const float*)d_in[3];
    const float* bproj = (const float*)d_in[4];
    float* out = (float*)d_out;

    cudaFuncSetAttribute(gemm_wm<0>,
                         cudaFuncAttributeMaxDynamicSharedMemorySize, GEMM_SMEM);
    cudaFuncSetAttribute(gemm_wm<1>,
                         cudaFuncAttributeMaxDynamicSharedMemorySize, GEMM_SMEM);
    cudaFuncSetAttribute(attn_wm,
                         cudaFuncAttributeMaxDynamicSharedMemorySize, ATT_SMEM);

    split_kernel<0><<<(M_ * D_) / 1024, 256>>>(x, M_ * D_);
    split_kernel<1><<<(NQKV * D_) / 1024, 256>>>(Wqkv, NQKV * D_);
    split_kernel<2><<<(D_ * D_) / 1024, 256>>>(Wproj, D_ * D_);

    gemm_wm<0><<<dim3(NQKV / 128, M_ / 128), 256, GEMM_SMEM>>>(bqkv, nullptr);

    attn_wm<<<dim3(T_ / 128, B_ * H_), 256, ATT_SMEM>>>();

    gemm_wm<1><<<dim3(D_ / 128, M_ / 128), 256, GEMM_SMEM>>>(bproj, out);
}

// round 8
// speedup vs baseline: 2.8927x; 1.1091x over previous
#include <cuda_runtime.h>
#include <cuda_bf16.h>
#include <cstdint>

// Problem constants
#define B_   2
#define T_   2048
#define D_   1024
#define H_   16
#define HD_  64
#define M_   (B_ * T_)       // 4096
#define NQKV (3 * D_)        // 3072
#define K_   D_              // 1024

// ---------------------------------------------------------------------------
// Scratch (__device__ globals: allocation-free rule)
// ---------------------------------------------------------------------------
__device__ __nv_bfloat16 g_xh[M_ * D_],    g_xl[M_ * D_];
__device__ __nv_bfloat16 g_wqh[NQKV * D_], g_wql[NQKV * D_];
__device__ __nv_bfloat16 g_wph[D_ * D_],   g_wpl[D_ * D_];
__device__ __nv_bfloat16 g_Qh[M_ * D_], g_Ql[M_ * D_];
__device__ __nv_bfloat16 g_Kh[M_ * D_], g_Kl[M_ * D_];
__device__ __nv_bfloat16 g_Vh[M_ * D_], g_Vl[M_ * D_];
__device__ __nv_bfloat16 g_oh[M_ * D_], g_ol[M_ * D_];

// ---------------------------------------------------------------------------
// Base-ISA tensor-core helpers (compute_103-safe: NO tcgen05)
// ---------------------------------------------------------------------------
__device__ __forceinline__ uint32_t smem_to_u32(const void* p) {
    uint32_t a;
    asm("{ .reg .u64 t; cvta.to.shared.u64 t, %1; cvt.u32.u64 %0, t; }"
        : "=r"(a) : "l"(p));
    return a;
}
__device__ __forceinline__ void ldsm4(uint32_t* r, uint32_t addr) {
    asm volatile("ldmatrix.sync.aligned.m8n8.x4.shared.b16 {%0,%1,%2,%3}, [%4];"
        : "=r"(r[0]), "=r"(r[1]), "=r"(r[2]), "=r"(r[3]) : "r"(addr));
}
__device__ __forceinline__ void ldsm4t(uint32_t* r, uint32_t addr) {
    asm volatile("ldmatrix.sync.aligned.m8n8.x4.trans.shared.b16 {%0,%1,%2,%3}, [%4];"
        : "=r"(r[0]), "=r"(r[1]), "=r"(r[2]), "=r"(r[3]) : "r"(addr));
}
__device__ __forceinline__ void mma16816(float* d, const uint32_t* a, const uint32_t* b) {
    asm volatile(
        "mma.sync.aligned.m16n8k16.row.col.f32.bf16.bf16.f32 "
        "{%0,%1,%2,%3}, {%4,%5,%6,%7}, {%8,%9}, {%0,%1,%2,%3};"
        : "+f"(d[0]), "+f"(d[1]), "+f"(d[2]), "+f"(d[3])
        : "r"(a[0]), "r"(a[1]), "r"(a[2]), "r"(a[3]), "r"(b[0]), "r"(b[1]));
}
#define CP_ASYNC16(s, g) \
    asm volatile("cp.async.cg.shared.global [%0], [%1], 16;" :: "r"(s), "l"(g))
#define CP_COMMIT() asm volatile("cp.async.commit_group;" ::: "memory")
#define CP_WAIT1()  asm volatile("cp.async.wait_group 1;" ::: "memory")
#define CP_WAIT0()  asm volatile("cp.async.wait_group 0;" ::: "memory")

__device__ __forceinline__ void split2(float x, float y, uint32_t& hi, uint32_t& lo) {
    __nv_bfloat16 hx = __float2bfloat16(x), hy = __float2bfloat16(y);
    __nv_bfloat162 hv(hx, hy);
    __nv_bfloat162 lv(__float2bfloat16(x - __bfloat162float(hx)),
                      __float2bfloat16(y - __bfloat162float(hy)));
    hi = *reinterpret_cast<uint32_t*>(&hv);
    lo = *reinterpret_cast<uint32_t*>(&lv);
}

// ---------------------------------------------------------------------------
// fp32 -> bf16 hi/lo split kernels.  SRC: 0=x, 1=W_qkv, 2=W_proj
// ---------------------------------------------------------------------------
template <int SRC>
__global__ __launch_bounds__(256)
void split_kernel(const float* __restrict__ src, int n)
{
    __nv_bfloat16 *h, *l;
    if      (SRC == 0) { h = g_xh;  l = g_xl;  }
    else if (SRC == 1) { h = g_wqh; l = g_wql; }
    else               { h = g_wph; l = g_wpl; }

    int i = (blockIdx.x * 256 + threadIdx.x) * 4;
    if (i >= n) return;
    float4 v = *(const float4*)(src + i);
    uint32_t h0, l0, h1, l1;
    split2(v.x, v.y, h0, l0);
    split2(v.z, v.w, h1, l1);
    uint32_t* hp = (uint32_t*)(h + i);
    uint32_t* lp = (uint32_t*)(l + i);
    hp[0] = h0; hp[1] = h1;
    lp[0] = l0; lp[1] = l1;
}

// ---------------------------------------------------------------------------
// Warp-MMA GEMM (HMMA bf16, 3-term split): C = A @ W^T + bias.
// __launch_bounds__(256, 2): pin regs <= 128 so 2 CTAs/SM stay resident
// (R6's 129-reg build fell off the occupancy cliff: 300us vs 249us).
// ---------------------------------------------------------------------------
#define ROWB        80u
#define TILE_BYTES  (128u * ROWB)
#define STAGE_BYTES (4u * TILE_BYTES)
#define GEMM_SMEM   (2 * (int)STAGE_BYTES)
#define NCH         (K_ / 32)

__device__ __forceinline__ void load_stage(
    uint32_t sbase,
    const __nv_bfloat16* __restrict__ Ah, const __nv_bfloat16* __restrict__ Al,
    const __nv_bfloat16* __restrict__ Bh, const __nv_bfloat16* __restrict__ Bl,
    int m0, int n0, int k0, int tid)
{
#pragma unroll
    for (int i = 0; i < 8; ++i) {
        const int arr = i >> 1;
        const int row = ((i & 1) << 6) + (tid >> 2);
        const int ck  = tid & 3;
        const __nv_bfloat16* src = (arr == 0) ? Ah : (arr == 1) ? Al
                                  : (arr == 2) ? Bh : Bl;
        const int grow = ((arr < 2) ? m0 : n0) + row;
        const void* g = (const char*)(src + (size_t)grow * K_ + k0) + ck * 16;
        uint32_t s = sbase + (uint32_t)arr * TILE_BYTES
                           + (uint32_t)row * ROWB + (uint32_t)ck * 16u;
        CP_ASYNC16(s, g);
    }
}

template <int MODE>
__global__ __launch_bounds__(256, 2)
void gemm_wm(const float* __restrict__ bias, float* __restrict__ out)
{
    extern __shared__ char smem[];

    const __nv_bfloat16* Ah = (MODE == 0) ? g_xh  : g_oh;
    const __nv_bfloat16* Al = (MODE == 0) ? g_xl  : g_ol;
    const __nv_bfloat16* Bh = (MODE == 0) ? g_wqh : g_wph;
    const __nv_bfloat16* Bl = (MODE == 0) ? g_wql : g_wpl;

    const int tid    = threadIdx.x;
    const int wid    = tid >> 5;
    const int lane   = tid & 31;
    const int m0     = blockIdx.y << 7;
    const int n0     = blockIdx.x << 7;
    const int warp_m = (wid >> 1) * 32;
    const int warp_n = (wid & 1) * 64;
    const uint32_t sb = smem_to_u32(smem);

    const int sub = lane >> 3, rin = lane & 7;
    const uint32_t a_ro = (uint32_t)((sub & 1) * 8 + rin) * ROWB
                        + (uint32_t)(sub >> 1) * 16u;
    const uint32_t b_ro = (uint32_t)((sub >> 1) * 8 + rin) * ROWB
                        + (uint32_t)(sub & 1) * 16u;

    float acc[2][8][4];
#pragma unroll
    for (int mt = 0; mt < 2; ++mt)
#pragma unroll
        for (int nt = 0; nt < 8; ++nt)
#pragma unroll
            for (int q = 0; q < 4; ++q) acc[mt][nt][q] = 0.f;

    load_stage(sb, Ah, Al, Bh, Bl, m0, n0, 0, tid);
    CP_COMMIT();

    for (int ch = 0; ch < NCH; ++ch) {
        const uint32_t st = sb + (uint32_t)(ch & 1) * STAGE_BYTES;
        __syncthreads();
        if (ch + 1 < NCH) {
            load_stage(sb + (uint32_t)((ch + 1) & 1) * STAGE_BYTES,
                       Ah, Al, Bh, Bl, m0, n0, (ch + 1) * 32, tid);
            CP_COMMIT();
            CP_WAIT1();
        } else {
            CP_WAIT0();
        }
        __syncthreads();

#pragma unroll
        for (int ks = 0; ks < 2; ++ks) {
            uint32_t ah[2][4], alr[2][4];
#pragma unroll
            for (int mt = 0; mt < 2; ++mt) {
                uint32_t ab = st + (uint32_t)(warp_m + mt * 16) * ROWB
                                 + a_ro + (uint32_t)ks * 32u;
                ldsm4(ah[mt],  ab);
                ldsm4(alr[mt], ab + TILE_BYTES);
            }
#pragma unroll
            for (int ng = 0; ng < 4; ++ng) {
                uint32_t bh[4], blr[4];
                uint32_t bbadr = st + 2u * TILE_BYTES
                               + (uint32_t)(warp_n + ng * 16) * ROWB
                               + b_ro + (uint32_t)ks * 32u;
                ldsm4(bh,  bbadr);
                ldsm4(blr, bbadr + TILE_BYTES);
#pragma unroll
                for (int mt = 0; mt < 2; ++mt)
#pragma unroll
                    for (int hf = 0; hf < 2; ++hf) {
                        float* d = acc[mt][ng * 2 + hf];
                        mma16816(d, ah[mt],  bh  + hf * 2);
                        mma16816(d, ah[mt],  blr + hf * 2);
                        mma16816(d, alr[mt], bh  + hf * 2);
                    }
            }
        }
    }

    const int qrow = lane >> 2;
    const int qcol = (lane & 3) * 2;
#pragma unroll
    for (int mt = 0; mt < 2; ++mt)
#pragma unroll
        for (int rr = 0; rr < 2; ++rr) {
            const int m  = m0 + warp_m + mt * 16 + qrow + rr * 8;
            const int bb = m >> 11;
            const int t  = m & (T_ - 1);
#pragma unroll
            for (int nt = 0; nt < 8; ++nt) {
                const int n = n0 + warp_n + nt * 8 + qcol;
                float vx = acc[mt][nt][rr * 2 + 0] + bias[n];
                float vy = acc[mt][nt][rr * 2 + 1] + bias[n + 1];
                if (MODE == 0) {
                    const int part = n >> 10;       // 0=Q 1=K 2=V
                    const int c    = n & (D_ - 1);
                    const int h    = c >> 6;
                    const int d    = c & (HD_ - 1);
                    __nv_bfloat16 *dh, *dl;
                    if      (part == 0) { dh = g_Qh; dl = g_Ql; }
                    else if (part == 1) { dh = g_Kh; dl = g_Kl; }
                    else                { dh = g_Vh; dl = g_Vl; }
                    size_t idx = ((size_t)(bb * H_ + h) * T_ + t) * HD_ + d;
                    uint32_t hi, lo;
                    split2(vx, vy, hi, lo);
                    *(uint32_t*)(dh + idx) = hi;
                    *(uint32_t*)(dl + idx) = lo;
                } else {
                    float2 v; v.x = vx; v.y = vy;
                    *(float2*)(out + (size_t)m * D_ + n) = v;
                }
            }
        }
}

// ---------------------------------------------------------------------------
// HMMA flash-attention (causal). CTA: 128 queries of one (b,h), 8 warps x 16
// rows. KV blocks of 64, cp.async double-buffered. 3-term bf16 split.
// Causal tile-skipping: warp-uniform guards drop S-tiles / PV k-slices that
// lie entirely above the causal boundary (their P is exactly 0).
// ---------------------------------------------------------------------------
#define AROWB        144u
#define Q_TILE_BYTES (128u * AROWB)     // 18432
#define KVT_BYTES    (64u * AROWB)      // 9216
#define ATT_STAGE    (4u * KVT_BYTES)   // 36864
#define ATT_SMEM     (int)(2u * Q_TILE_BYTES + 2u * ATT_STAGE)  // 110592

__device__ __forceinline__ void attn_load_kv(uint32_t sk, size_t base, int kb0, int tid)
{
#pragma unroll
    for (int i = 0; i < 8; ++i) {
        const int arr = i >> 1;                     // 0 Kh,1 Kl,2 Vh,3 Vl
        const int row = ((i & 1) << 5) + (tid >> 3);
        const int ck  = tid & 7;
        const __nv_bfloat16* src = (arr == 0) ? g_Kh : (arr == 1) ? g_Kl
                                  : (arr == 2) ? g_Vh : g_Vl;
        const void* g = src + base + (size_t)(kb0 + row) * HD_ + ck * 8;
        uint32_t s = sk + (uint32_t)arr * KVT_BYTES
                        + (uint32_t)row * AROWB + (uint32_t)ck * 16u;
        CP_ASYNC16(s, g);
    }
}

__global__ __launch_bounds__(256)
void attn_wm()
{
    extern __shared__ char smem[];
    const uint32_t sb   = smem_to_u32(smem);
    const uint32_t sQ   = sb;
    const uint32_t sKV0 = sb + 2u * Q_TILE_BYTES;

    const int tid    = threadIdx.x;
    const int wid    = tid >> 5;
    const int lane   = tid & 31;
    const int qb     = (int)gridDim.x - 1 - (int)blockIdx.x;   // heavy first
    const int bh     = blockIdx.y;
    const int q0     = qb << 7;
    const size_t base = (size_t)bh * (T_ * HD_);
    const int warp_m = wid * 16;
    const int nblk   = 2 * (qb + 1);
    const int wlast  = q0 + warp_m + 15;    // last valid col for this warp
    const float scale = 0.125f;

    const int sub = lane >> 3, rin = lane & 7;
    const uint32_t a_ro = (uint32_t)((sub & 1) * 8 + rin) * AROWB
                        + (uint32_t)(sub >> 1) * 16u;
    const uint32_t b_ro = (uint32_t)((sub >> 1) * 8 + rin) * AROWB
                        + (uint32_t)(sub & 1) * 16u;

#pragma unroll
    for (int i = 0; i < 8; ++i) {
        const int arr = i >> 2;                     // 0 Qh, 1 Ql
        const int row = ((i & 3) << 5) + (tid >> 3);
        const int ck  = tid & 7;
        const __nv_bfloat16* src = arr ? g_Ql : g_Qh;
        const void* g = src + base + (size_t)(q0 + row) * HD_ + ck * 8;
        uint32_t s = sQ + (uint32_t)arr * Q_TILE_BYTES
                        + (uint32_t)row * AROWB + (uint32_t)ck * 16u;
        CP_ASYNC16(s, g);
    }
    CP_COMMIT();
    attn_load_kv(sKV0, base, 0, tid);
    CP_COMMIT();
    CP_WAIT1();
    __syncthreads();

    uint32_t qh[4][4], ql[4][4];
#pragma unroll
    for (int ks = 0; ks < 4; ++ks) {
        uint32_t ab = sQ + (uint32_t)warp_m * AROWB + a_ro + (uint32_t)ks * 32u;
        ldsm4(qh[ks], ab);
        ldsm4(ql[ks], ab + Q_TILE_BYTES);
    }

    float oacc[8][4];
#pragma unroll
    for (int nt = 0; nt < 8; ++nt)
#pragma unroll
        for (int q = 0; q < 4; ++q) oacc[nt][q] = 0.f;
    float m0r = -1e30f, m1r = -1e30f, l0r = 0.f, l1r = 0.f;

    const int qrow = lane >> 2;
    const int qcol = (lane & 3) * 2;
    const int rg0  = q0 + warp_m + qrow;

    for (int jb = 0; jb < nblk; ++jb) {
        const uint32_t st = sKV0 + (uint32_t)(jb & 1) * ATT_STAGE;
        const int kb0 = jb << 6;
        __syncthreads();
        if (jb + 1 < nblk) {
            attn_load_kv(sKV0 + (uint32_t)((jb + 1) & 1) * ATT_STAGE,
                         base, (jb + 1) << 6, tid);
            CP_COMMIT();
            CP_WAIT1();
        } else {
            CP_WAIT0();
        }
        __syncthreads();

        // Warp-uniform: this whole KV block is above the causal boundary
        const bool block_dead = (kb0 > wlast);
        if (!block_dead) {
            // ---- S = Q K^T ----
            float s[8][4];
#pragma unroll
            for (int nt = 0; nt < 8; ++nt)
#pragma unroll
                for (int q = 0; q < 4; ++q) s[nt][q] = 0.f;

#pragma unroll
            for (int ntile = 0; ntile < 4; ++ntile) {
                if (kb0 + ntile * 16 > wlast) break;   // warp-uniform causal skip
#pragma unroll
                for (int ks = 0; ks < 4; ++ks) {
                    uint32_t kh[4], kl[4];
                    uint32_t ad = st + (uint32_t)(ntile * 16) * AROWB
                                     + b_ro + (uint32_t)ks * 32u;
                    ldsm4(kh, ad);
                    ldsm4(kl, ad + KVT_BYTES);
#pragma unroll
                    for (int hf = 0; hf < 2; ++hf) {
                        float* d = s[ntile * 2 + hf];
                        mma16816(d, qh[ks], kh + hf * 2);
                        mma16816(d, qh[ks], kl + hf * 2);
                        mma16816(d, ql[ks], kh + hf * 2);
                    }
                }
            }

            // ---- causal mask (near-diagonal blocks) ----
            if (kb0 + 63 > q0 + warp_m) {
#pragma unroll
                for (int nt = 0; nt < 8; ++nt) {
                    int cg = kb0 + nt * 8 + qcol;
                    if (cg     > rg0)     s[nt][0] = -1e30f;
                    if (cg + 1 > rg0)     s[nt][1] = -1e30f;
                    if (cg     > rg0 + 8) s[nt][2] = -1e30f;
                    if (cg + 1 > rg0 + 8) s[nt][3] = -1e30f;
                }
            }

            // ---- online softmax ----
            float mx0 = -1e30f, mx1 = -1e30f;
#pragma unroll
            for (int nt = 0; nt < 8; ++nt) {
                mx0 = fmaxf(mx0, fmaxf(s[nt][0], s[nt][1]));
                mx1 = fmaxf(mx1, fmaxf(s[nt][2], s[nt][3]));
            }
            mx0 = fmaxf(mx0, __shfl_xor_sync(0xffffffffu, mx0, 1));
            mx0 = fmaxf(mx0, __shfl_xor_sync(0xffffffffu, mx0, 2));
            mx1 = fmaxf(mx1, __shfl_xor_sync(0xffffffffu, mx1, 1));
            mx1 = fmaxf(mx1, __shfl_xor_sync(0xffffffffu, mx1, 2));
            float mn0 = fmaxf(m0r, mx0 * scale);
            float mn1 = fmaxf(m1r, mx1 * scale);

            uint32_t ph[8][2], pl[8][2];
            float sum0 = 0.f, sum1 = 0.f;
#pragma unroll
            for (int nt = 0; nt < 8; ++nt) {
                float p0 = __expf(fmaf(s[nt][0], scale, -mn0));
                float p1 = __expf(fmaf(s[nt][1], scale, -mn0));
                float p2 = __expf(fmaf(s[nt][2], scale, -mn1));
                float p3 = __expf(fmaf(s[nt][3], scale, -mn1));
                sum0 += p0 + p1;
                sum1 += p2 + p3;
                split2(p0, p1, ph[nt][0], pl[nt][0]);
                split2(p2, p3, ph[nt][1], pl[nt][1]);
            }
            sum0 += __shfl_xor_sync(0xffffffffu, sum0, 1);
            sum0 += __shfl_xor_sync(0xffffffffu, sum0, 2);
            sum1 += __shfl_xor_sync(0xffffffffu, sum1, 1);
            sum1 += __shfl_xor_sync(0xffffffffu, sum1, 2);

            float f0 = __expf(m0r - mn0);
            float f1 = __expf(m1r - mn1);
            l0r = l0r * f0 + sum0;
            l1r = l1r * f1 + sum1;
            m0r = mn0; m1r = mn1;
#pragma unroll
            for (int nt = 0; nt < 8; ++nt) {
                oacc[nt][0] *= f0; oacc[nt][1] *= f0;
                oacc[nt][2] *= f1; oacc[nt][3] *= f1;
            }

            // ---- O += P V ----
#pragma unroll
            for (int ks = 0; ks < 4; ++ks) {
                if (kb0 + ks * 16 > wlast) break;      // P identically 0 there
                uint32_t ah[4] = { ph[2 * ks][0], ph[2 * ks][1],
                                   ph[2 * ks + 1][0], ph[2 * ks + 1][1] };
                uint32_t al[4] = { pl[2 * ks][0], pl[2 * ks][1],
                                   pl[2 * ks + 1][0], pl[2 * ks + 1][1] };
#pragma unroll
                for (int dnt = 0; dnt < 4; ++dnt) {
                    uint32_t vh[4], vl[4];
                    uint32_t ad = st + 2u * KVT_BYTES
                                + (uint32_t)(ks * 16) * AROWB
                                + a_ro + (uint32_t)dnt * 32u;
                    ldsm4t(vh, ad);
                    ldsm4t(vl, ad + KVT_BYTES);
#pragma unroll
                    for (int hf = 0; hf < 2; ++hf) {
                        float* d = oacc[dnt * 2 + hf];
                        mma16816(d, ah, vh + hf * 2);
                        mma16816(d, al, vh + hf * 2);
                        mma16816(d, ah, vl + hf * 2);
                    }
                }
            }
        }
    }

    // ---- epilogue ----
    const int bb = bh >> 4;
    const int h  = bh & 15;
    const float inv0 = 1.0f / l0r;
    const float inv1 = 1.0f / l1r;
    const int t0 = q0 + warp_m + qrow;
#pragma unroll
    for (int nt = 0; nt < 8; ++nt) {
        const int d = nt * 8 + qcol;
        uint32_t hi, lo;
        size_t i0 = (size_t)(bb * T_ + t0) * D_ + h * HD_ + d;
        split2(oacc[nt][0] * inv0, oacc[nt][1] * inv0, hi, lo);
        *(uint32_t*)(g_oh + i0) = hi;
        *(uint32_t*)(g_ol + i0) = lo;
        size_t i1 = (size_t)(bb * T_ + t0 + 8) * D_ + h * HD_ + d;
        split2(oacc[nt][2] * inv1, oacc[nt][3] * inv1, hi, lo);
        *(uint32_t*)(g_oh + i1) = hi;
        *(uint32_t*)(g_ol + i1) = lo;
    }
}

// ---------------------------------------------------------------------------
// kernel_launch
// ---------------------------------------------------------------------------
extern "C" void kernel_launch(void* const* d_in, const int* in_sizes, int n_in,
                              void* d_out, int out_size)
{
    (void)in_sizes; (void)n_in; (void)out_size;
    const float* x     = (const float*)d_in[0];
    const float* Wqkv  = (const float*)d_in[1];
    const float* bqkv  = (const float*)d_in[2];
    const float* Wproj = (const float*)d_in[3];
    const float* bproj = (const float*)d_in[4];
    float* out = (float*)d_out;

    cudaFuncSetAttribute(gemm_wm<0>,
                         cudaFuncAttributeMaxDynamicSharedMemorySize, GEMM_SMEM);
    cudaFuncSetAttribute(gemm_wm<1>,
                         cudaFuncAttributeMaxDynamicSharedMemorySize, GEMM_SMEM);
    cudaFuncSetAttribute(attn_wm,
                         cudaFuncAttributeMaxDynamicSharedMemorySize, ATT_SMEM);

    split_kernel<0><<<(M_ * D_) / 1024, 256>>>(x, M_ * D_);
    split_kernel<1><<<(NQKV * D_) / 1024, 256>>>(Wqkv, NQKV * D_);
    split_kernel<2><<<(D_ * D_) / 1024, 256>>>(Wproj, D_ * D_);

    gemm_wm<0><<<dim3(NQKV / 128, M_ / 128), 256, GEMM_SMEM>>>(bqkv, nullptr);

    attn_wm<<<dim3(T_ / 128, B_ * H_), 256, ATT_SMEM>>>();

    gemm_wm<1><<<dim3(D_ / 128, M_ / 128), 256, GEMM_SMEM>>>(bproj, out);
}